// round 7
// baseline (speedup 1.0000x reference)
#include <cuda_runtime.h>
#include <cuda_fp16.h>
#include <stdint.h>

// Problem constants (fixed by the dataset)
#define N_NODES 50000    // divisible by 8 -> clean 8-nodes-per-warp proj
#define IN_DIM  128
#define N_EDGES 500000   // divisible by 2 -> no tail in the edge kernel

#define EDGE_CTAS    64      // ~sqrt(gather_work / broadcast_cost) optimum
#define EDGE_THREADS 1024
#define TABLE_BYTES  (N_NODES * 4)   // 50000 x half2 = 195.3 KB

// Packed per-node projections: g_pair[n] = (proj_src[n], proj_dst[n]) as half2.
__device__ __half2 g_pair[N_NODES];

// ---------------------------------------------------------------------------
// Kernel 1: node projection. EIGHT nodes per warp -> 8 independent LDG.128
// streams per warp (MLP=8). Weight halves are L1-hot. Results packed to
// half2 and written as 2x 16B coalesced stores by lane 0.
// ---------------------------------------------------------------------------
__global__ __launch_bounds__(256) void proj_kernel(const float* __restrict__ x,
                                                   const float* __restrict__ W) {
    const int warp_id = (blockIdx.x * blockDim.x + threadIdx.x) >> 5;
    const int lane    = threadIdx.x & 31;
    const int base    = warp_id * 8;
    if (base >= N_NODES) return;

    const float4 wa = reinterpret_cast<const float4*>(W)[lane];            // W[:128]
    const float4 wb = reinterpret_cast<const float4*>(W + IN_DIM)[lane];   // W[128:]

    float4 xv[8];
    #pragma unroll
    for (int i = 0; i < 8; i++)
        xv[i] = reinterpret_cast<const float4*>(x + (size_t)(base + i) * IN_DIM)[lane];

    float sa[8], sb[8];
    #pragma unroll
    for (int i = 0; i < 8; i++) {
        sa[i] = xv[i].x * wa.x + xv[i].y * wa.y + xv[i].z * wa.z + xv[i].w * wa.w;
        sb[i] = xv[i].x * wb.x + xv[i].y * wb.y + xv[i].z * wb.z + xv[i].w * wb.w;
    }

    #pragma unroll
    for (int off = 16; off > 0; off >>= 1) {
        #pragma unroll
        for (int i = 0; i < 8; i++) {
            sa[i] += __shfl_xor_sync(0xFFFFFFFFu, sa[i], off);
            sb[i] += __shfl_xor_sync(0xFFFFFFFFu, sb[i], off);
        }
    }

    if (lane == 0) {
        __half2 p[8];
        #pragma unroll
        for (int i = 0; i < 8; i++) p[i] = __floats2half2_rn(sa[i], sb[i]);
        // base multiple of 8 -> 16B-aligned; two coalesced 16B stores
        reinterpret_cast<uint4*>(g_pair + base)[0] = *reinterpret_cast<uint4*>(p);
        reinterpret_cast<uint4*>(g_pair + base)[1] = *reinterpret_cast<uint4*>(p + 4);
    }
}

// ---------------------------------------------------------------------------
// Sigmoid with one MUFU op: sigmoid(x) = 0.5*tanh(x/2) + 0.5
// ---------------------------------------------------------------------------
__device__ __forceinline__ float sigmoid_tanh(float v) {
    float t;
    asm("tanh.approx.f32 %0, %1;" : "=f"(t) : "f"(0.5f * v));
    return fmaf(0.5f, t, 0.5f);
}

// ---------------------------------------------------------------------------
// Kernel 2: stage the full 195KB half2 projection table in shared memory,
// then gather via LDS (crossbar, ~4 conflict phases for random addresses)
// instead of L1tex warp-gathers (~30 wavefronts x 2.07cyc each — the floor
// measured in R5/R6). Grid-stride over int2-edge units.
// ---------------------------------------------------------------------------
__global__ __launch_bounds__(EDGE_THREADS, 1)
void edge_kernel(const int* __restrict__ edge_index,
                 const float* __restrict__ edge_weight,
                 const float* __restrict__ b,
                 float* __restrict__ out) {
    extern __shared__ __half2 s_tab[];   // N_NODES half2 = 195.3 KB

    // Cooperative table load: 12500 x 16B, fully coalesced (L2-broadcast)
    {
        const uint4* src = reinterpret_cast<const uint4*>(g_pair);
        uint4*       dst = reinterpret_cast<uint4*>(s_tab);
        for (int i = threadIdx.x; i < TABLE_BYTES / 16; i += EDGE_THREADS)
            dst[i] = src[i];
    }
    __syncthreads();

    const float bias = b[0];
    const int   stride = gridDim.x * EDGE_THREADS;

    for (int t = blockIdx.x * EDGE_THREADS + threadIdx.x;
         t < N_EDGES / 2; t += stride) {
        const int2   sv = reinterpret_cast<const int2*>(edge_index)[t];
        const int2   dv = reinterpret_cast<const int2*>(edge_index + N_EDGES)[t];
        const float2 wv = reinterpret_cast<const float2*>(edge_weight)[t];

        const int s0 = min(max(sv.x, 0), N_NODES - 1), s1 = min(max(sv.y, 0), N_NODES - 1);
        const int d0 = min(max(dv.x, 0), N_NODES - 1), d1 = min(max(dv.y, 0), N_NODES - 1);

        // 4 smem gathers (LDS.32), conflict-degree-bounded, no L1tex wavefronts
        const float ps0 = __low2float(s_tab[s0]);
        const float ps1 = __low2float(s_tab[s1]);
        const float pd0 = __high2float(s_tab[d0]);
        const float pd1 = __high2float(s_tab[d1]);

        float2 r;
        r.x = wv.x * sigmoid_tanh(ps0 + pd0 + bias);
        r.y = wv.y * sigmoid_tanh(ps1 + pd1 + bias);
        reinterpret_cast<float2*>(out)[t] = r;
    }
}

// ---------------------------------------------------------------------------
// Launch. Inputs (metadata order): x, edge_index, edge_weight, W, b.
// ---------------------------------------------------------------------------
extern "C" void kernel_launch(void* const* d_in, const int* in_sizes, int n_in,
                              void* d_out, int out_size) {
    const float* x  = (const float*)d_in[0];
    const int*   ei = (const int*)d_in[1];
    const float* ew = (const float*)d_in[2];
    const float* W  = (const float*)d_in[3];
    const float* b  = (const float*)d_in[4];
    float*       o  = (float*)d_out;

    // Opt-in to >48KB dynamic smem (idempotent host-side config, not captured)
    cudaFuncSetAttribute(edge_kernel,
                         cudaFuncAttributeMaxDynamicSharedMemorySize, TABLE_BYTES);

    // Kernel 1: eight nodes per warp -> 6250 warps
    {
        const int threads = 256;
        const int warps_per_block = threads / 32;
        const int node_groups = N_NODES / 8;                 // 6250
        const int blocks = (node_groups + warps_per_block - 1) / warps_per_block;
        proj_kernel<<<blocks, threads>>>(x, W);
    }
    // Kernel 2: smem-table gather kernel
    edge_kernel<<<EDGE_CTAS, EDGE_THREADS, TABLE_BYTES>>>(ei, ew, b, o);
}

// round 8
// speedup vs baseline: 1.2575x; 1.2575x over previous
#include <cuda_runtime.h>
#include <cuda_fp16.h>
#include <stdint.h>

// Problem constants (fixed by the dataset)
#define N_NODES 50000    // divisible by 8 -> clean 8-nodes-per-warp proj
#define IN_DIM  128
#define N_EDGES 500000   // divisible by 2 -> no tail in the edge kernel

#define EDGE_CTAS    96
#define EDGE_THREADS 1024
#define TABLE_BYTES  (N_NODES * 4)        // 50000 x half2 = 195.3 KB
#define TABLE_VEC16  (TABLE_BYTES / 16)   // 12500 16B chunks

// Packed per-node projections: g_pair[n] = (proj_src[n], proj_dst[n]) as half2.
__device__ __half2 g_pair[N_NODES];

// ---------------------------------------------------------------------------
// Kernel 1: node projection. EIGHT nodes per warp -> 8 independent LDG.128
// streams per warp (MLP=8). Weight halves are L1-hot. Results packed to
// half2 and written as 2x 16B coalesced stores by lane 0.  (R7: confirmed
// ~3.7us including launch gap.)
// ---------------------------------------------------------------------------
__global__ __launch_bounds__(256) void proj_kernel(const float* __restrict__ x,
                                                   const float* __restrict__ W) {
    const int warp_id = (blockIdx.x * blockDim.x + threadIdx.x) >> 5;
    const int lane    = threadIdx.x & 31;
    const int base    = warp_id * 8;
    if (base >= N_NODES) return;

    const float4 wa = reinterpret_cast<const float4*>(W)[lane];            // W[:128]
    const float4 wb = reinterpret_cast<const float4*>(W + IN_DIM)[lane];   // W[128:]

    float4 xv[8];
    #pragma unroll
    for (int i = 0; i < 8; i++)
        xv[i] = reinterpret_cast<const float4*>(x + (size_t)(base + i) * IN_DIM)[lane];

    float sa[8], sb[8];
    #pragma unroll
    for (int i = 0; i < 8; i++) {
        sa[i] = xv[i].x * wa.x + xv[i].y * wa.y + xv[i].z * wa.z + xv[i].w * wa.w;
        sb[i] = xv[i].x * wb.x + xv[i].y * wb.y + xv[i].z * wb.z + xv[i].w * wb.w;
    }

    #pragma unroll
    for (int off = 16; off > 0; off >>= 1) {
        #pragma unroll
        for (int i = 0; i < 8; i++) {
            sa[i] += __shfl_xor_sync(0xFFFFFFFFu, sa[i], off);
            sb[i] += __shfl_xor_sync(0xFFFFFFFFu, sb[i], off);
        }
    }

    if (lane == 0) {
        __half2 p[8];
        #pragma unroll
        for (int i = 0; i < 8; i++) p[i] = __floats2half2_rn(sa[i], sb[i]);
        reinterpret_cast<uint4*>(g_pair + base)[0] = *reinterpret_cast<uint4*>(p);
        reinterpret_cast<uint4*>(g_pair + base)[1] = *reinterpret_cast<uint4*>(p + 4);
    }
}

// ---------------------------------------------------------------------------
// Sigmoid with one MUFU op: sigmoid(x) = 0.5*tanh(x/2) + 0.5
// ---------------------------------------------------------------------------
__device__ __forceinline__ float sigmoid_tanh(float v) {
    float t;
    asm("tanh.approx.f32 %0, %1;" : "=f"(t) : "f"(0.5f * v));
    return fmaf(0.5f, t, 0.5f);
}

__device__ __forceinline__ void cp_async16(uint32_t smem_dst, const void* gmem_src) {
    asm volatile("cp.async.cg.shared.global [%0], [%1], 16;"
                 :: "r"(smem_dst), "l"(gmem_src));
}

// ---------------------------------------------------------------------------
// Kernel 2: stage the 195KB half2 projection table in shared memory via
// cp.async (LDGSTS: no register staging, deep LSU queue -> fixes the R7
// MLP~1 serialization), overlap the staging with prefetch of iteration-0
// edge data, then gather via LDS (random 4B: ~4-5 conflict phases/warp,
// vs ~30 L1tex wavefronts for global gathers).
// ---------------------------------------------------------------------------
__global__ __launch_bounds__(EDGE_THREADS, 1)
void edge_kernel(const int* __restrict__ edge_index,
                 const float* __restrict__ edge_weight,
                 const float* __restrict__ b,
                 float* __restrict__ out) {
    extern __shared__ __half2 s_tab[];   // N_NODES half2 = 195.3 KB

    const int tid = threadIdx.x;

    // --- Issue table staging: 12500 x cp.async.cg 16B, fully coalesced ---
    {
        uint32_t s_base = (uint32_t)__cvta_generic_to_shared(s_tab);
        const char* g_base = reinterpret_cast<const char*>(g_pair);
        for (int i = tid; i < TABLE_VEC16; i += EDGE_THREADS)
            cp_async16(s_base + i * 16, g_base + i * 16);
        asm volatile("cp.async.commit_group;");
    }

    // --- Prefetch iteration-0 edge data while the table streams in ---
    // grid*block = 98304 <= N_EDGES/2, so iteration 0 is always in range.
    const int t0     = blockIdx.x * EDGE_THREADS + tid;
    const int stride = EDGE_CTAS * EDGE_THREADS;
    int2   sv0 = reinterpret_cast<const int2*>(edge_index)[t0];
    int2   dv0 = reinterpret_cast<const int2*>(edge_index + N_EDGES)[t0];
    float2 wv0 = reinterpret_cast<const float2*>(edge_weight)[t0];
    const float bias = b[0];

    // --- Wait for table, make it visible to all warps ---
    asm volatile("cp.async.wait_group 0;");
    __syncthreads();

    // --- Iteration 0 (prefetched) ---
    {
        const int s0 = min(max(sv0.x, 0), N_NODES - 1), s1 = min(max(sv0.y, 0), N_NODES - 1);
        const int d0 = min(max(dv0.x, 0), N_NODES - 1), d1 = min(max(dv0.y, 0), N_NODES - 1);
        const float ps0 = __low2float(s_tab[s0]),  ps1 = __low2float(s_tab[s1]);
        const float pd0 = __high2float(s_tab[d0]), pd1 = __high2float(s_tab[d1]);
        float2 r;
        r.x = wv0.x * sigmoid_tanh(ps0 + pd0 + bias);
        r.y = wv0.y * sigmoid_tanh(ps1 + pd1 + bias);
        reinterpret_cast<float2*>(out)[t0] = r;
    }

    // --- Remaining grid-stride iterations ---
    for (int t = t0 + stride; t < N_EDGES / 2; t += stride) {
        const int2   sv = reinterpret_cast<const int2*>(edge_index)[t];
        const int2   dv = reinterpret_cast<const int2*>(edge_index + N_EDGES)[t];
        const float2 wv = reinterpret_cast<const float2*>(edge_weight)[t];

        const int s0 = min(max(sv.x, 0), N_NODES - 1), s1 = min(max(sv.y, 0), N_NODES - 1);
        const int d0 = min(max(dv.x, 0), N_NODES - 1), d1 = min(max(dv.y, 0), N_NODES - 1);

        const float ps0 = __low2float(s_tab[s0]),  ps1 = __low2float(s_tab[s1]);
        const float pd0 = __high2float(s_tab[d0]), pd1 = __high2float(s_tab[d1]);

        float2 r;
        r.x = wv.x * sigmoid_tanh(ps0 + pd0 + bias);
        r.y = wv.y * sigmoid_tanh(ps1 + pd1 + bias);
        reinterpret_cast<float2*>(out)[t] = r;
    }
}

// ---------------------------------------------------------------------------
// Launch. Inputs (metadata order): x, edge_index, edge_weight, W, b.
// ---------------------------------------------------------------------------
extern "C" void kernel_launch(void* const* d_in, const int* in_sizes, int n_in,
                              void* d_out, int out_size) {
    const float* x  = (const float*)d_in[0];
    const int*   ei = (const int*)d_in[1];
    const float* ew = (const float*)d_in[2];
    const float* W  = (const float*)d_in[3];
    const float* b  = (const float*)d_in[4];
    float*       o  = (float*)d_out;

    // Opt-in to >48KB dynamic smem (idempotent host-side config, not captured)
    cudaFuncSetAttribute(edge_kernel,
                         cudaFuncAttributeMaxDynamicSharedMemorySize, TABLE_BYTES);

    // Kernel 1: eight nodes per warp -> 6250 warps
    {
        const int threads = 256;
        const int warps_per_block = threads / 32;
        const int node_groups = N_NODES / 8;                 // 6250
        const int blocks = (node_groups + warps_per_block - 1) / warps_per_block;
        proj_kernel<<<blocks, threads>>>(x, W);
    }
    // Kernel 2: smem-table gather kernel
    edge_kernel<<<EDGE_CTAS, EDGE_THREADS, TABLE_BYTES>>>(ei, ew, b, o);
}